// round 2
// baseline (speedup 1.0000x reference)
#include <cuda_runtime.h>
#include <math.h>

#define Bb 2048
#define Mm 64
#define Dd 512
#define NROWS (Bb*Mm)     // 131072
#define NC    2560        // 5*512 stacked: [zr | zw | zf | zi | zc]
#define BK    16

// ---------------- scratch (device globals; no runtime allocation) ----------------
__device__ float g_WtBig[Dd*NC];   // stacked W1[:, :D]  transposed -> [k][c]
__device__ float g_WtX  [Dd*NC];   // stacked W1[:, D:]  transposed -> [k][c]
__device__ float g_WtFin[Dd*Dd];   // Wfin^T  [k][d]
__device__ float g_WtSub[Dd*Dd];   // Wsub^T  [k][d]
__device__ float g_bstack[NC];
__device__ float g_xterm[Bb*NC];   // x @ WtX + bstack
__device__ float g_F[NROWS*Dd];
__device__ float g_I[NROWS*Dd];
__device__ float g_C[NROWS*Dd];
__device__ float g_mem[NROWS*Dd];
__device__ float g_sRp[NROWS*8];   // partial h_r . W2r per 64-col chunk
__device__ float g_sWp[NROWS*8];
__device__ float g_simr[NROWS];
__device__ float g_simw[NROWS];
__device__ float g_subvec[Bb*Dd];

// ---------------- weight transpose / stacking ----------------
__global__ void prep_k(const float* __restrict__ W1r, const float* __restrict__ W1w,
                       const float* __restrict__ Wf,  const float* __restrict__ Wi,
                       const float* __restrict__ Wc,
                       const float* __restrict__ b1r, const float* __restrict__ b1w,
                       const float* __restrict__ bf,  const float* __restrict__ bi,
                       const float* __restrict__ bc,
                       const float* __restrict__ Wfin, const float* __restrict__ Wsub)
{
    int idx = blockIdx.x*blockDim.x + threadIdx.x;
    int stride = gridDim.x*blockDim.x;
    for (int i = idx; i < Dd*NC; i += stride) {
        int k = i / NC, c = i % NC;
        int j = c >> 9, d = c & 511;
        const float* W = (j==0)?W1r:(j==1)?W1w:(j==2)?Wf:(j==3)?Wi:Wc;
        g_WtBig[i] = W[d*(2*Dd) + k];
        g_WtX[i]   = W[d*(2*Dd) + Dd + k];
        if (i < Dd*Dd) {
            int kk = i >> 9, dd = i & 511;
            g_WtFin[i] = Wfin[dd*Dd + kk];
            g_WtSub[i] = Wsub[dd*Dd + kk];
        }
        if (i < NC) {
            const float* bb = (j==0)?b1r:(j==1)?b1w:(j==2)?bf:(j==3)?bi:bc;
            g_bstack[i] = bb[d];
        }
    }
}

// ---------------- fused tiled GEMM (BM=64, BN=64, BK=16, 4x4 micro-tile) ----------
// epi: 0 = xterm (out=g_xterm, +bstack)
//      1 = main  (A=sub_memory; per-j activations; F/I/C + s partials)
//      2 = fin   (A=g_subvec, W=WtFin, tanh, -> out[b,0,:])
//      3 = sub   (A=g_mem,   W=WtSub, tanh, -> out[b,1+m,:])
__global__ void __launch_bounds__(256)
gemm_k(int epi, const float* __restrict__ Ain,
       const float* __restrict__ bias,
       const float* __restrict__ w2r, const float* __restrict__ w2w,
       float* __restrict__ out)
{
    __shared__ float As[BK][68];
    __shared__ float Ws[BK][68];
    __shared__ float w2s[64];
    __shared__ float red[64][17];

    const int tid = threadIdx.x;
    const int tm = tid & 15;      // m-group 0..15
    const int td = tid >> 4;      // n-group 0..15
    const int chunk  = blockIdx.x;
    const int rowblk = blockIdx.y;
    const int row0 = rowblk * 64;
    const int n0   = chunk * 64;

    const float* A;
    const float* W;
    int ldw;
    if (epi == 0)      { A = Ain;      W = g_WtX;   ldw = NC; }
    else if (epi == 1) { A = Ain;      W = g_WtBig; ldw = NC; }
    else if (epi == 2) { A = g_subvec; W = g_WtFin; ldw = Dd; }
    else               { A = g_mem;    W = g_WtSub; ldw = Dd; }

    int jmat = 0;
    if (epi == 1) {
        jmat = chunk >> 3;
        if (jmat == 0 && tid < 64) w2s[tid] = w2r[(chunk & 7)*64 + tid];
        if (jmat == 1 && tid < 64) w2s[tid] = w2w[(chunk & 7)*64 + tid];
    }

    const int ar = tid >> 2;        // 0..63
    const int ak = (tid & 3) * 4;   // 0,4,8,12
    const int wk = tid >> 4;        // 0..15
    const int wn = (tid & 15) * 4;  // 0..60

    float acc[4][4];
#pragma unroll
    for (int i=0;i<4;i++)
#pragma unroll
        for (int jj=0;jj<4;jj++) acc[i][jj]=0.f;

    for (int k0 = 0; k0 < Dd; k0 += BK) {
        __syncthreads();
        float4 av = *(const float4*)&A[(row0+ar)*Dd + k0 + ak];
        As[ak+0][ar]=av.x; As[ak+1][ar]=av.y; As[ak+2][ar]=av.z; As[ak+3][ar]=av.w;
        float4 wv = *(const float4*)&W[(k0+wk)*ldw + n0 + wn];
        *(float4*)&Ws[wk][wn] = wv;
        __syncthreads();
#pragma unroll
        for (int k=0;k<BK;k++){
            float4 a = *(const float4*)&As[k][tm*4];
            float4 b = *(const float4*)&Ws[k][td*4];
            acc[0][0] += a.x*b.x; acc[0][1] += a.x*b.y; acc[0][2] += a.x*b.z; acc[0][3] += a.x*b.w;
            acc[1][0] += a.y*b.x; acc[1][1] += a.y*b.y; acc[1][2] += a.y*b.z; acc[1][3] += a.y*b.w;
            acc[2][0] += a.z*b.x; acc[2][1] += a.z*b.y; acc[2][2] += a.z*b.z; acc[2][3] += a.z*b.w;
            acc[3][0] += a.w*b.x; acc[3][1] += a.w*b.y; acc[3][2] += a.w*b.z; acc[3][3] += a.w*b.w;
        }
    }

    if (epi == 0) {
        // xterm = x @ WtX + bstack  (bias from global stack)
#pragma unroll
        for (int i=0;i<4;i++){
            int r = row0 + tm*4 + i;
#pragma unroll
            for (int jj=0;jj<4;jj++){
                int c = n0 + td*4 + jj;
                g_xterm[r*NC + c] = acc[i][jj] + g_bstack[c];
            }
        }
    } else if (epi == 1) {
        int b = rowblk;
        int ch8 = chunk & 7;
        if (jmat <= 1) {
            // h = relu(z); partial dot with W2 over this 64-col d-range
            float pr[4] = {0.f,0.f,0.f,0.f};
#pragma unroll
            for (int i=0;i<4;i++){
#pragma unroll
                for (int jj=0;jj<4;jj++){
                    int c = n0 + td*4 + jj;
                    float z = acc[i][jj] + g_xterm[b*NC + c];
                    float h = fmaxf(z, 0.f);
                    pr[i] += h * w2s[td*4 + jj];
                }
            }
            __syncthreads();
#pragma unroll
            for (int i=0;i<4;i++) red[tm*4+i][td] = pr[i];
            __syncthreads();
            if (tid < 64) {
                float s = 0.f;
#pragma unroll
                for (int t=0;t<16;t++) s += red[tid][t];
                float* dst = (jmat==0) ? g_sRp : g_sWp;
                dst[(b*64 + tid)*8 + ch8] = s;
            }
        } else {
            float* dst = (jmat==2) ? g_F : (jmat==3) ? g_I : g_C;
#pragma unroll
            for (int i=0;i<4;i++){
                int m = tm*4 + i;
                int d0 = ch8*64 + td*4;
                float zv[4];
#pragma unroll
                for (int jj=0;jj<4;jj++)
                    zv[jj] = acc[i][jj] + g_xterm[b*NC + n0 + td*4 + jj];
                float4 v;
                if (jmat == 4) {
                    v.x = tanhf(zv[0]); v.y = tanhf(zv[1]); v.z = tanhf(zv[2]); v.w = tanhf(zv[3]);
                } else {
                    v.x = 1.f/(1.f+expf(-zv[0])); v.y = 1.f/(1.f+expf(-zv[1]));
                    v.z = 1.f/(1.f+expf(-zv[2])); v.w = 1.f/(1.f+expf(-zv[3]));
                }
                *(float4*)&dst[(b*64 + m)*Dd + d0] = v;
            }
        }
    } else {
        // epi 2: read_vec row -> out[b,0,:]; epi 3: new_mem -> out[b,1+m,:]
#pragma unroll
        for (int i=0;i<4;i++){
            int r = row0 + tm*4 + i;
            int c0 = n0 + td*4;
            int outbase;
            if (epi == 2) outbase = r * (65*512);
            else          outbase = (r + (r >> 6) + 1) * 512;
            float4 v;
            v.x = tanhf(acc[i][0] + bias[c0+0]);
            v.y = tanhf(acc[i][1] + bias[c0+1]);
            v.z = tanhf(acc[i][2] + bias[c0+2]);
            v.w = tanhf(acc[i][3] + bias[c0+3]);
            *(float4*)&out[outbase + c0] = v;
        }
    }
}

// ---------------- softmax over M=64 (deterministic, block per batch) -------------
__global__ void softmax_k() {
    int b = blockIdx.x, m = threadIdx.x;
    float sr = 0.f, sw = 0.f;
    const float* pr = &g_sRp[(b*64+m)*8];
    const float* pw = &g_sWp[(b*64+m)*8];
#pragma unroll
    for (int p=0;p<8;p++){ sr += pr[p]; sw += pw[p]; }

    __shared__ float sh[64];
    // r-softmax
    sh[m] = sr; __syncthreads();
    for (int s=32;s>0;s>>=1){ if(m<s) sh[m]=fmaxf(sh[m],sh[m+s]); __syncthreads(); }
    float mxr = sh[0]; __syncthreads();
    float er = expf(sr - mxr);
    sh[m] = er; __syncthreads();
    for (int s=32;s>0;s>>=1){ if(m<s) sh[m]+=sh[m+s]; __syncthreads(); }
    float sumr = sh[0]; __syncthreads();
    g_simr[b*64+m] = er / sumr;
    // w-softmax
    sh[m] = sw; __syncthreads();
    for (int s=32;s>0;s>>=1){ if(m<s) sh[m]=fmaxf(sh[m],sh[m+s]); __syncthreads(); }
    float mxw = sh[0]; __syncthreads();
    float ew = expf(sw - mxw);
    sh[m] = ew; __syncthreads();
    for (int s=32;s>0;s>>=1){ if(m<s) sh[m]+=sh[m+s]; __syncthreads(); }
    float sumw = sh[0]; __syncthreads();
    g_simw[b*64+m] = ew / sumw;
}

// ---------------- sub_vec = sum_m sub_memory * sim_r -----------------------------
__global__ void subvec_k(const float* __restrict__ sub) {
    int b = blockIdx.x, d = threadIdx.x;      // 512 threads
    __shared__ float ss[64];
    if (d < 64) ss[d] = g_simr[b*64 + d];
    __syncthreads();
    const float* base = sub + (size_t)b*64*512 + d;
    float acc = 0.f;
#pragma unroll
    for (int m=0;m<64;m++) acc += base[m*512] * ss[m];
    g_subvec[b*512 + d] = acc;
}

// ---------------- mem = (1 - sw*f)*sub + i*c*sw ----------------------------------
__global__ void mem_k(const float* __restrict__ sub) {
    int i4 = blockIdx.x*blockDim.x + threadIdx.x;   // float4 index
    const int n4 = NROWS*Dd/4;                      // 16,777,216
    if (i4 >= n4) return;
    int r = i4 >> 7;                                // (i4*4)/512
    float sw = g_simw[r];
    float4 s  = ((const float4*)sub)[i4];
    float4 f  = ((const float4*)g_F)[i4];
    float4 ii = ((const float4*)g_I)[i4];
    float4 c  = ((const float4*)g_C)[i4];
    float4 o;
    o.x = (1.f - sw*f.x)*s.x + ii.x*c.x*sw;
    o.y = (1.f - sw*f.y)*s.y + ii.y*c.y*sw;
    o.z = (1.f - sw*f.z)*s.z + ii.z*c.z*sw;
    o.w = (1.f - sw*f.w)*s.w + ii.w*c.w*sw;
    ((float4*)g_mem)[i4] = o;
}

// ---------------- launch ----------------------------------------------------------
extern "C" void kernel_launch(void* const* d_in, const int* in_sizes, int n_in,
                              void* d_out, int out_size)
{
    const float* x    = (const float*)d_in[0];
    const float* sub  = (const float*)d_in[1];
    const float* W1r  = (const float*)d_in[2];
    const float* b1r  = (const float*)d_in[3];
    const float* W2r  = (const float*)d_in[4];
    /* b2r = d_in[5]  -- softmax-invariant, unused */
    const float* W1w  = (const float*)d_in[6];
    const float* b1w  = (const float*)d_in[7];
    const float* W2w  = (const float*)d_in[8];
    /* b2w = d_in[9]  -- unused */
    const float* Wf   = (const float*)d_in[10];
    const float* bf   = (const float*)d_in[11];
    const float* Wi   = (const float*)d_in[12];
    const float* bi   = (const float*)d_in[13];
    const float* Wc   = (const float*)d_in[14];
    const float* bc   = (const float*)d_in[15];
    const float* Wsub = (const float*)d_in[16];
    const float* bsub = (const float*)d_in[17];
    const float* Wfin = (const float*)d_in[18];
    const float* bfin = (const float*)d_in[19];
    float* out = (float*)d_out;

    // 1. transpose/stack weights + bias stack
    prep_k<<<2048, 256>>>(W1r, W1w, Wf, Wi, Wc, b1r, b1w, bf, bi, bc, Wfin, Wsub);

    // 2. xterm = x @ WtX + bstack   [2048 x 2560]
    gemm_k<<<dim3(40, 32), 256>>>(0, x, nullptr, nullptr, nullptr, nullptr);

    // 3. main fused GEMM: sub_memory @ WtBig + xterm -> s partials, F, I, C
    gemm_k<<<dim3(40, 2048), 256>>>(1, sub, nullptr, W2r, W2w, nullptr);

    // 4. softmax over slots
    softmax_k<<<2048, 64>>>();

    // 5. read attention pooling
    subvec_k<<<2048, 512>>>(sub);

    // 6. gated memory update (elementwise)
    mem_k<<<(NROWS*Dd/4 + 255)/256, 256>>>(sub);

    // 7. read_vec = tanh(sub_vec @ Wfin^T + bfin) -> out[b,0,:]
    gemm_k<<<dim3(8, 32), 256>>>(2, nullptr, bfin, nullptr, nullptr, out);

    // 8. new_mem = tanh(mem @ Wsub^T + bsub) -> out[b,1+m,:]
    gemm_k<<<dim3(8, 2048), 256>>>(3, nullptr, bsub, nullptr, nullptr, out);
}